// round 14
// baseline (speedup 1.0000x reference)
#include <cuda_runtime.h>
#include <cuda_pipeline_primitives.h>

// CGMMTransition: N=10000, L=5, A=6, C=20, C2=20
// Tiles = thirds of an n (10 la-rows each), 2 tiles per block, cp.async
// pipelined: tile1's stats prefetch hides under tile0's store stream.
// Outputs (concatenated in d_out, fp32):
//   p_Q_given_obs        [N, C]           at offset 0
//   transition_posterior [N, L, A, C, C2] at offset N*C
//   rightmost_term       [N, L, A, C, C2] at offset N*C + N*L*A*C*C2

#define LVAL   5
#define AVAL   6
#define CVAL   20
#define C2VAL  20
#define LA     30      // L*A
#define LAT    10      // la rows per tile
#define KDIM   600     // LA*C2
#define KDIMT  200     // stats floats per tile
#define PER_N  12000   // LA*C*C2
#define PER_T4 1000    // float4s per tile
#define NTHREADS 256
#define NWARPS 8
#define NITER  4       // ceil(1000/256); iter 3 partial (tid < 232)
#define TAIL   (PER_T4 - 3 * NTHREADS)    // 232

__global__ void zero_pq_kernel(float* __restrict__ out_pq, int total)
{
    int i = blockIdx.x * blockDim.x + threadIdx.x;
    if (i < total) out_pq[i] = 0.0f;
}

// One tile's 1000-float4 stream (R13 body, unchanged).
__device__ __forceinline__ void stream_tile(
    const float4* __restrict__ T4t,       // T + tile's f4 offset
    float4* __restrict__ rt4,             // out_rt + tile's f4 offset
    float4* __restrict__ tp4,             // out_tp + tile's f4 offset
    const float* __restrict__ st,         // s_stats bank
    const float* __restrict__ sinv,       // s_inv bank
    const float* __restrict__ sw,         // s_w bank
    float (*bins)[CVAL],                  // [NWARPS][CVAL] bank
    int tid, int warp, int lane)
{
    // division-free index state for local i = tid + 256*k (element e = 4*i):
    //   m = i%5 (c2 block = 4m), c = (i/5)%20, la = i/100 in [0,10)
    int m    = tid % 5;
    int c    = (tid / 5) % CVAL;
    int la   = tid / 100;
    int r100 = tid % 100;

    #pragma unroll
    for (int k = 0; k < NITER; ++k) {
        const int  i   = tid + k * NTHREADS;
        const bool act = (k < NITER - 1) || (tid < TAIL);

        float v = 0.0f;
        if (act) {
            const float4 t  = __ldg(&T4t[i]);   // L1-resident, coalesced
            const float4 sv = *reinterpret_cast<const float4*>(
                                  st + la * C2VAL + 4 * m);
            const float inv = sinv[la];
            const float w   = sw[la];
            float4 r, p;
            r.x = t.x * sv.x * inv;  r.y = t.y * sv.y * inv;
            r.z = t.z * sv.z * inv;  r.w = t.w * sv.w * inv;
            p.x = r.x * w;  p.y = r.y * w;  p.z = r.z * w;  p.w = r.w * w;
            __stcs(&rt4[i], r);   // streaming stores
            __stcs(&tp4[i], p);
            v = (p.x + p.y) + (p.z + p.w);
        }

        // segmented reduction over runs of 5 equal-c lanes (d = 1,2,4)
        float o;
        o = __shfl_down_sync(0xFFFFFFFFu, v, 1);
        if (m <= 3 && lane < 31) v += o;
        o = __shfl_down_sync(0xFFFFFFFFu, v, 2);
        if (m <= 2 && lane < 30) v += o;
        o = __shfl_down_sync(0xFFFFFFFFu, v, 4);
        if (m == 0 && lane < 28) v += o;

        // head lanes have distinct c within a warp-iter -> plain RMW safe
        if (m == 0 || lane == 0) bins[warp][c] += v;

        const bool wrap = (m == 4);
        m = wrap ? 0 : m + 1;
        c += wrap ? 12 : 11;
        if (c >= CVAL) c -= CVAL;
        la += 2; r100 += 56;
        if (r100 >= 100) { la += 1; r100 -= 100; }
    }
}

__global__ void __launch_bounds__(NTHREADS, 8)
cgmm_kernel(const float* __restrict__ stats,
            const float* __restrict__ layerS,
            const float* __restrict__ arcS,
            const float* __restrict__ T,
            float* __restrict__ out_pq,
            float* __restrict__ out_tp,
            float* __restrict__ out_rt,
            int ntiles)
{
    __shared__ float s_stats[2][KDIMT];
    __shared__ float s_inv[2][LAT];
    __shared__ float s_w[2][LAT];
    __shared__ float s_pqw[2][NWARPS][CVAL];

    const int tid  = threadIdx.x;
    const int warp = tid >> 5;
    const int lane = tid & 31;

    const int t0 = blockIdx.x * 2;
    const int t1 = t0 + 1;
    const bool has1 = (t1 < ntiles);

    const int n0 = t0 / 3, h0 = t0 - 3 * n0;
    const int n1 = t1 / 3, h1 = t1 - 3 * n1;   // unused if !has1

    // ---- prologue: async-copy tile0 stats (50 chunks; guard < 256 OK) ----
    if (tid < KDIMT / 4)
        __pipeline_memcpy_async(&s_stats[0][tid * 4],
                                stats + (size_t)n0 * KDIM + h0 * KDIMT + tid * 4,
                                16);
    __pipeline_commit();

    // zero ALL 2*8*20 = 320 bin entries (320 > 256: stride!)
    for (int q = tid; q < 2 * NWARPS * CVAL; q += NTHREADS)
        reinterpret_cast<float*>(s_pqw)[q] = 0.0f;
    // weights for both tiles (20 < 256 OK; indices in-bounds even if !has1)
    if (tid < 2 * LAT) {
        const int sel = tid / LAT, r = tid % LAT;
        const int la0 = (sel ? h1 : h0) * LAT;
        s_w[sel][r] = layerS[(la0 + r) / AVAL] * arcS[la0 + r];
    }

    __pipeline_wait_prior(0);
    __syncthreads();

    if (tid < LAT) {
        float s = 0.0f;
        #pragma unroll
        for (int j = 0; j < C2VAL; ++j) s += s_stats[0][tid * C2VAL + j];
        s_inv[0][tid] = (s == 0.0f) ? 1.0f : 1.0f / s;
    }
    __syncthreads();

    // ---- prefetch tile1 stats; lands while tile0 streams ----
    if (has1 && tid < KDIMT / 4)
        __pipeline_memcpy_async(&s_stats[1][tid * 4],
                                stats + (size_t)n1 * KDIM + h1 * KDIMT + tid * 4,
                                16);
    __pipeline_commit();

    // ---- stream tile0 ----
    {
        const size_t b4 = (size_t)n0 * (PER_N / 4) + h0 * PER_T4;
        stream_tile(reinterpret_cast<const float4*>(T) + h0 * PER_T4,
                    reinterpret_cast<float4*>(out_rt) + b4,
                    reinterpret_cast<float4*>(out_tp) + b4,
                    s_stats[0], s_inv[0], s_w[0], s_pqw[0],
                    tid, warp, lane);
    }

    __pipeline_wait_prior(0);
    __syncthreads();   // tile0 bins complete; tile1 stats staged

    if (has1 && tid < LAT) {
        float s = 0.0f;
        #pragma unroll
        for (int j = 0; j < C2VAL; ++j) s += s_stats[1][tid * C2VAL + j];
        s_inv[1][tid] = (s == 0.0f) ? 1.0f : 1.0f / s;
    }
    // flush tile0's p_Q partial (20 < 256 OK)
    if (tid < CVAL) {
        float s = 0.0f;
        #pragma unroll
        for (int w8 = 0; w8 < NWARPS; ++w8) s += s_pqw[0][w8][tid];
        atomicAdd(&out_pq[(size_t)n0 * CVAL + tid], s);
    }
    __syncthreads();   // s_inv[1] visible

    // ---- stream tile1 ----
    if (has1) {
        const size_t b4 = (size_t)n1 * (PER_N / 4) + h1 * PER_T4;
        stream_tile(reinterpret_cast<const float4*>(T) + h1 * PER_T4,
                    reinterpret_cast<float4*>(out_rt) + b4,
                    reinterpret_cast<float4*>(out_tp) + b4,
                    s_stats[1], s_inv[1], s_w[1], s_pqw[1],
                    tid, warp, lane);

        __syncthreads();
        if (tid < CVAL) {
            float s = 0.0f;
            #pragma unroll
            for (int w8 = 0; w8 < NWARPS; ++w8) s += s_pqw[1][w8][tid];
            atomicAdd(&out_pq[(size_t)n1 * CVAL + tid], s);
        }
    }
}

extern "C" void kernel_launch(void* const* d_in, const int* in_sizes, int n_in,
                              void* d_out, int out_size)
{
    const float* stats  = (const float*)d_in[0];  // [N, L, A, C2]
    const float* layerS = (const float*)d_in[1];  // [L]
    const float* arcS   = (const float*)d_in[2];  // [L, A]
    const float* T      = (const float*)d_in[3];  // [L, A, C, C2]

    const int N = in_sizes[0] / KDIM;

    float* out    = (float*)d_out;
    float* out_pq = out;
    float* out_tp = out_pq + (size_t)N * CVAL;
    float* out_rt = out_tp + (size_t)N * PER_N;

    const int pq_total = N * CVAL;
    zero_pq_kernel<<<(pq_total + NTHREADS - 1) / NTHREADS, NTHREADS>>>(
        out_pq, pq_total);

    const int ntiles = 3 * N;
    const int grid   = (ntiles + 1) / 2;
    cgmm_kernel<<<grid, NTHREADS>>>(stats, layerS, arcS, T,
                                    out_pq, out_tp, out_rt, ntiles);
}